// round 16
// baseline (speedup 1.0000x reference)
#include <cuda_runtime.h>
#include <cstdint>

// FilterTransform: cascaded biquads (fixed HP + random coeffs) over time,
// x[4096,16000] and n[4096,16000] -> out [8192,16000].
//
// R13 (from R12 @168.9us): the per-tile fence.proxy.async was issued right
// after the top syncwarp, when all lanes' STS of tile g-1 were still in
// flight (MEMBAR drain = 36 + ~10 * n_STS -> hundreds of cycles). The fence
// is now issued INSIDE the compute loop at j==15, ~350 cyc after the last
// STS, just before the bulk stores begin at j==16. Result STS predicated to
// real lanes to shrink the drain set.

static constexpr int T_LEN   = 16000;
static constexpr int HALF    = 4096;
static constexpr int SEG     = 32;                  // float4 per row per tile (512B)
static constexpr int NTILES  = (T_LEN / 4) / SEG;   // 125
static constexpr int ROWS    = 14;                  // real rows per block (1 warp)
static constexpr int XBLOCKS = (HALF + ROWS - 1) / ROWS;  // 293
static constexpr int PAD     = 1;
static constexpr int NBUF    = 6;
static constexpr int SROWS   = ROWS + 1;            // +1 scratch row (lanes 14..31)
static constexpr int ROW_BYTES = SEG * 16;          // 512

__device__ __forceinline__ void cp_async16(uint32_t saddr, const void* gptr) {
    asm volatile("cp.async.cg.shared.global [%0], [%1], 16;"
                 :: "r"(saddr), "l"(gptr) : "memory");
}
__device__ __forceinline__ void cp_commit() {
    asm volatile("cp.async.commit_group;" ::: "memory");
}
__device__ __forceinline__ void cp_wait2() {
    asm volatile("cp.async.wait_group 2;" ::: "memory");
}
__device__ __forceinline__ void bulk_s2g(void* gdst, uint32_t ssrc, uint32_t bytes) {
    asm volatile("cp.async.bulk.global.shared::cta.bulk_group [%0], [%1], %2;"
                 :: "l"(gdst), "r"(ssrc), "r"(bytes) : "memory");
}
__device__ __forceinline__ void bulk_commit() {
    asm volatile("cp.async.bulk.commit_group;" ::: "memory");
}
__device__ __forceinline__ void bulk_wait_read1() {
    asm volatile("cp.async.bulk.wait_group.read 1;" ::: "memory");
}
__device__ __forceinline__ void bulk_wait_all() {
    asm volatile("cp.async.bulk.wait_group 0;" ::: "memory");
}
__device__ __forceinline__ void fence_async_shared() {
    asm volatile("fence.proxy.async.shared::cta;" ::: "memory");
}
__device__ __forceinline__ float fma_imm1(float a, float c) {
    // a*1.0 + c as FFMA-imm (rt 1); bit-identical to a + c.
    float d;
    asm("fma.rn.f32 %0, %1, 0f3F800000, %2;" : "=f"(d) : "f"(a), "f"(c));
    return d;
}

__global__ __launch_bounds__(32)
void biquad_cascade_kernel(const float* __restrict__ x,
                           const float* __restrict__ n,
                           const float* __restrict__ a_x,
                           const float* __restrict__ b_x,
                           const float* __restrict__ a_n,
                           const float* __restrict__ b_n,
                           float* __restrict__ out)
{
    __shared__ float4 tile[NBUF][SROWS][SEG + PAD];

    const int lane = threadIdx.x;
    const bool is_x = (blockIdx.x < XBLOCKS);
    const int bi = is_x ? blockIdx.x : blockIdx.x - XBLOCKS;
    const int rowbase = bi * ROWS;
    const int nrows = (HALF - rowbase) < ROWS ? (HALF - rowbase) : ROWS;

    const float* inbase = is_x ? (x + (size_t)rowbase * T_LEN)
                               : (n + (size_t)rowbase * T_LEN);
    float* outbase = out + (size_t)(is_x ? rowbase : rowbase + HALF) * T_LEN;

    float b0, b1, na0, na1;
    if (is_x) { na0 = -a_x[0]; na1 = -a_x[1]; b0 = b_x[0]; b1 = b_x[1]; }
    else      { na0 = -a_n[0]; na1 = -a_n[1]; b0 = b_n[0]; b1 = b_n[1]; }

    // Stage 1 (HP) DF2T state; stage 2 DF-I histories.
    float m0 = 0.f, m1 = 0.f;
    float u1 = 0.f, u2 = 0.f, v1 = 0.f, v2 = 0.f;

    const bool leader = (lane == 0);
    const bool real   = (lane < nrows);                 // lanes that own a row
    const int myRowIdx = (lane < ROWS) ? lane : ROWS;   // scratch row for hi lanes

    auto issue_tile = [&](int g, int slot) {
        const float* src = inbase + (size_t)g * (SEG * 4) + lane * 4;
        #pragma unroll
        for (int i = 0; i < ROWS; i++) {
            const int rr = (i < nrows) ? i : (nrows - 1);
            uint32_t saddr = (uint32_t)__cvta_generic_to_shared(&tile[slot][i][lane]);
            cp_async16(saddr, src + (size_t)rr * T_LEN);
        }
    };

    issue_tile(0, 0); cp_commit();
    issue_tile(1, 1); cp_commit();
    issue_tile(2, 2); cp_commit();

    int slot  = 0;                         // g % NBUF
    int sslot = NBUF - 1;                  // (g-1) % NBUF  (store slot)
    int rslot = 3;                         // (g+3) % NBUF  (refill slot)

    for (int g = 0; g < NTILES; g++) {
        cp_wait2();              // tile g's loads landed (<=2 newer groups pending)
        if (leader) bulk_wait_read1();   // refill target (tile g-3 slot) reads drained
        __syncwarp();            // publish STS of tile g-1 + leader's wait to all

        const bool do_refill = (g + 3 < NTILES);
        const bool do_store  = (g > 0);

        const float* rsrc = inbase + (size_t)(do_refill ? (g + 3) : 0) * (SEG * 4)
                            + lane * 4;
        uint32_t rbase = (uint32_t)__cvta_generic_to_shared(&tile[rslot][0][lane]);
        float* dst_prev = outbase + (size_t)(g - 1) * (SEG * 4);
        uint32_t sbase = (uint32_t)__cvta_generic_to_shared(&tile[sslot][0][0]);

        float4* myrow = &tile[slot][myRowIdx][0];
        float4 vA = myrow[0];
        float4 vB = myrow[1];

        #pragma unroll
        for (int j = 0; j < SEG; j++) {
            float4 vin = vA;
            vA = vB;
            if (j + 2 < SEG) vB = myrow[j + 2];        // LDS prefetch distance 2

            if (j < ROWS) {                            // refill tile g+3 (all lanes)
                const int rr = (j < nrows) ? j : (nrows - 1);
                if (do_refill)
                    cp_async16(rbase + (uint32_t)(j * (SEG + PAD) * 16),
                               rsrc + (size_t)rr * T_LEN);
            } else if (j == 15) {
                // Fence AFTER tile g-1's STS have had ~15 samples to drain:
                // orders generic-proxy STS before async-proxy bulk reads below.
                if (leader && do_store) fence_async_shared();
            } else if (j >= 16 && j < 16 + ROWS) {     // store tile g-1 (lane 0)
                const int i = j - 16;
                if (do_store && leader && i < nrows)
                    bulk_s2g(dst_prev + (size_t)i * T_LEN,
                             sbase + (uint32_t)(i * (SEG + PAD) * 16), ROW_BYTES);
            }

            float xs[4] = {vin.x, vin.y, vin.z, vin.w};
            float ys[4];
            #pragma unroll
            for (int k = 0; k < 4; k++) {
                const float xv = xs[k];
                // Stage 1: exact DF2T high-pass (all FFMA-imm rt1)
                const float y1 = fma_imm1(xv, m0);
                m0 = fmaf(1.99599f, y1, fmaf(-2.0f, xv, m1));
                m1 = fmaf(-0.996f, y1, xv);
                // Stage 2: DF-I with runtime coeffs (well-damped poles)
                float s = fmaf(b0, u1, y1);
                s = fmaf(b1, u2, s);
                s = fmaf(na1, v2, s);
                const float v = fmaf(na0, v1, s);
                u2 = u1; u1 = y1;
                v2 = v1; v1 = v;
                ys[k] = v;
            }
            if (real) myrow[j] = make_float4(ys[0], ys[1], ys[2], ys[3]);
        }
        cp_commit();                       // one load group per tile
        if (leader) bulk_commit();         // one store group per tile (may be empty)

        slot  = (slot  + 1 == NBUF) ? 0 : slot  + 1;
        sslot = (sslot + 1 == NBUF) ? 0 : sslot + 1;
        rslot = (rslot + 1 == NBUF) ? 0 : rslot + 1;
    }

    // Epilogue: store the final tile (its slot == sslot now).
    __syncwarp();
    if (leader) {
        fence_async_shared();
        float* dst = outbase + (size_t)(NTILES - 1) * (SEG * 4);
        for (int i = 0; i < nrows; i++) {
            uint32_t ssrc = (uint32_t)__cvta_generic_to_shared(&tile[sslot][i][0]);
            bulk_s2g(dst + (size_t)i * T_LEN, ssrc, ROW_BYTES);
        }
        bulk_commit();
        bulk_wait_all();                   // all bulk stores complete before exit
    }
}

extern "C" void kernel_launch(void* const* d_in, const int* in_sizes, int n_in,
                              void* d_out, int out_size)
{
    const float* x   = (const float*)d_in[0];
    const float* n   = (const float*)d_in[1];
    const float* a_x = (const float*)d_in[2];
    const float* b_x = (const float*)d_in[3];
    const float* a_n = (const float*)d_in[4];
    const float* b_n = (const float*)d_in[5];
    float* out = (float*)d_out;

    biquad_cascade_kernel<<<2 * XBLOCKS, 32>>>(x, n, a_x, b_x, a_n, b_n, out);
}